// round 9
// baseline (speedup 1.0000x reference)
#include <cuda_runtime.h>
#include <math.h>
#include <stdint.h>

namespace {

constexpr int B  = 4;
constexpr int N  = 2048;
constexpr int D  = 1024;
constexpr int H  = 16;
constexpr int HD = 64;
constexpr int RD = 32;
constexpr int M  = B * N;   // 8192

// -------- scratch (device globals: allocation-guard safe) --------
__device__ float g_q[M * D];
__device__ float g_k[M * D];
__device__ float g_v[M * D];
__device__ float g_o[M * D];

__device__ __forceinline__ uint32_t f32_to_tf32(float x) {
    uint32_t y;
    asm("cvt.rna.tf32.f32 %0, %1;" : "=r"(y) : "f"(x));
    return y;
}

__device__ __forceinline__ void mma_tf32(
    float& d0, float& d1, float& d2, float& d3,
    uint32_t a0, uint32_t a1, uint32_t a2, uint32_t a3,
    uint32_t b0, uint32_t b1)
{
    asm volatile(
        "mma.sync.aligned.m16n8k8.row.col.f32.tf32.tf32.f32 "
        "{%0,%1,%2,%3}, {%4,%5,%6,%7}, {%8,%9}, {%0,%1,%2,%3};"
        : "+f"(d0), "+f"(d1), "+f"(d2), "+f"(d3)
        : "r"(a0), "r"(a1), "r"(a2), "r"(a3), "r"(b0), "r"(b1));
}

// ===== TF32 tensor-core GEMM, double-buffered software pipeline ============
// 128x128x16 tile, 256 threads (8 warps), warp tile 64x32.
// Pipeline: LDG(next tile)->regs issued BEFORE compute(current); cvt+STS into
// the alternate smem buffer after compute; one __syncthreads per K-tile.
constexpr int TBM = 128, TBN = 128, TBK = 16;
constexpr int ASTR = TBM + 4;   // 132
constexpr int SSTR = TBN + 4;   // 132

__global__ __launch_bounds__(256, 2) void tf32_gemm_bias_kernel(
    const float* __restrict__ A, const float* __restrict__ W,
    const float* __restrict__ bias, float* __restrict__ C,
    int Nd, int Kd)
{
    __shared__ uint32_t As[2][TBK][ASTR];
    __shared__ uint32_t Bs[2][TBK][SSTR];

    const int tid  = threadIdx.x;
    const int wid  = tid >> 5;
    const int lane = tid & 31;
    const int g    = lane >> 2;
    const int tig  = lane & 3;

    const int warp_m = (wid >> 2) * 64;
    const int warp_n = (wid & 3) * 32;

    const int brow0 = blockIdx.y * TBM;
    const int bcol0 = blockIdx.x * TBN;

    float acc[4][4][4];
#pragma unroll
    for (int mt = 0; mt < 4; mt++)
#pragma unroll
        for (int nt = 0; nt < 4; nt++)
#pragma unroll
            for (int r = 0; r < 4; r++) acc[mt][nt][r] = 0.0f;

    const float* Aptr = A + (size_t)brow0 * Kd;
    const float* Wptr = W + bcol0;

    // loader mapping (per thread: 2 A-float4, 2 B-float4 per tile)
    const int aRow0 = tid >> 2,               aCol0 = (tid & 3) * 4;
    const int aRow1 = (tid + 256) >> 2,       aCol1 = aCol0;          // (fid&3) identical
    const int bRow0 = tid >> 5,               bCol0v = (tid & 31) * 4;
    const int bRow1 = (tid + 256) >> 5,       bCol1v = bCol0v;

    float4 avr[2], wvr[2];

    // ---- prologue: load tile 0 into regs, store to buffer 0 ----
    avr[0] = *(const float4*)(Aptr + (size_t)aRow0 * Kd + aCol0);
    avr[1] = *(const float4*)(Aptr + (size_t)aRow1 * Kd + aCol1);
    wvr[0] = *(const float4*)(Wptr + (size_t)bRow0 * Nd + bCol0v);
    wvr[1] = *(const float4*)(Wptr + (size_t)bRow1 * Nd + bCol1v);

    As[0][aCol0 + 0][aRow0] = f32_to_tf32(avr[0].x);
    As[0][aCol0 + 1][aRow0] = f32_to_tf32(avr[0].y);
    As[0][aCol0 + 2][aRow0] = f32_to_tf32(avr[0].z);
    As[0][aCol0 + 3][aRow0] = f32_to_tf32(avr[0].w);
    As[0][aCol1 + 0][aRow1] = f32_to_tf32(avr[1].x);
    As[0][aCol1 + 1][aRow1] = f32_to_tf32(avr[1].y);
    As[0][aCol1 + 2][aRow1] = f32_to_tf32(avr[1].z);
    As[0][aCol1 + 3][aRow1] = f32_to_tf32(avr[1].w);
    {
        uint4 t0, t1;
        t0.x = f32_to_tf32(wvr[0].x); t0.y = f32_to_tf32(wvr[0].y);
        t0.z = f32_to_tf32(wvr[0].z); t0.w = f32_to_tf32(wvr[0].w);
        t1.x = f32_to_tf32(wvr[1].x); t1.y = f32_to_tf32(wvr[1].y);
        t1.z = f32_to_tf32(wvr[1].z); t1.w = f32_to_tf32(wvr[1].w);
        *(uint4*)&Bs[0][bRow0][bCol0v] = t0;
        *(uint4*)&Bs[0][bRow1][bCol1v] = t1;
    }
    __syncthreads();

    int buf = 0;
    for (int k0 = 0; k0 < Kd; k0 += TBK) {
        const bool have_next = (k0 + TBK) < Kd;

        // issue next tile's global loads early (overlap with compute)
        if (have_next) {
            const int kn = k0 + TBK;
            avr[0] = *(const float4*)(Aptr + (size_t)aRow0 * Kd + kn + aCol0);
            avr[1] = *(const float4*)(Aptr + (size_t)aRow1 * Kd + kn + aCol1);
            wvr[0] = *(const float4*)(Wptr + (size_t)(kn + bRow0) * Nd + bCol0v);
            wvr[1] = *(const float4*)(Wptr + (size_t)(kn + bRow1) * Nd + bCol1v);
        }

        // compute from current buffer
#pragma unroll
        for (int kk = 0; kk < TBK; kk += 8) {
            uint32_t af[4][4], bf[4][2];
#pragma unroll
            for (int mt = 0; mt < 4; mt++) {
                const int rm = warp_m + mt * 16;
                af[mt][0] = As[buf][kk + tig    ][rm + g    ];
                af[mt][1] = As[buf][kk + tig    ][rm + g + 8];
                af[mt][2] = As[buf][kk + tig + 4][rm + g    ];
                af[mt][3] = As[buf][kk + tig + 4][rm + g + 8];
            }
#pragma unroll
            for (int nt = 0; nt < 4; nt++) {
                const int cn = warp_n + nt * 8;
                bf[nt][0] = Bs[buf][kk + tig    ][cn + g];
                bf[nt][1] = Bs[buf][kk + tig + 4][cn + g];
            }
#pragma unroll
            for (int mt = 0; mt < 4; mt++)
#pragma unroll
                for (int nt = 0; nt < 4; nt++)
                    mma_tf32(acc[mt][nt][0], acc[mt][nt][1],
                             acc[mt][nt][2], acc[mt][nt][3],
                             af[mt][0], af[mt][1], af[mt][2], af[mt][3],
                             bf[nt][0], bf[nt][1]);
        }

        // stage next tile into the other buffer
        if (have_next) {
            const int nb = buf ^ 1;
            As[nb][aCol0 + 0][aRow0] = f32_to_tf32(avr[0].x);
            As[nb][aCol0 + 1][aRow0] = f32_to_tf32(avr[0].y);
            As[nb][aCol0 + 2][aRow0] = f32_to_tf32(avr[0].z);
            As[nb][aCol0 + 3][aRow0] = f32_to_tf32(avr[0].w);
            As[nb][aCol1 + 0][aRow1] = f32_to_tf32(avr[1].x);
            As[nb][aCol1 + 1][aRow1] = f32_to_tf32(avr[1].y);
            As[nb][aCol1 + 2][aRow1] = f32_to_tf32(avr[1].z);
            As[nb][aCol1 + 3][aRow1] = f32_to_tf32(avr[1].w);
            uint4 t0, t1;
            t0.x = f32_to_tf32(wvr[0].x); t0.y = f32_to_tf32(wvr[0].y);
            t0.z = f32_to_tf32(wvr[0].z); t0.w = f32_to_tf32(wvr[0].w);
            t1.x = f32_to_tf32(wvr[1].x); t1.y = f32_to_tf32(wvr[1].y);
            t1.z = f32_to_tf32(wvr[1].z); t1.w = f32_to_tf32(wvr[1].w);
            *(uint4*)&Bs[nb][bRow0][bCol0v] = t0;
            *(uint4*)&Bs[nb][bRow1][bCol1v] = t1;
            __syncthreads();
            buf = nb;
        }
    }

    // epilogue: bias + store
#pragma unroll
    for (int mt = 0; mt < 4; mt++) {
#pragma unroll
        for (int nt = 0; nt < 4; nt++) {
            const int col = bcol0 + warp_n + nt * 8 + tig * 2;
            const float b0 = bias[col], b1 = bias[col + 1];
            const size_t r0 = (size_t)(brow0 + warp_m + mt * 16 + g);
            const size_t r1 = r0 + 8;
            float2 v0 = make_float2(acc[mt][nt][0] + b0, acc[mt][nt][1] + b1);
            float2 v1 = make_float2(acc[mt][nt][2] + b0, acc[mt][nt][3] + b1);
            *(float2*)(C + r0 * Nd + col) = v0;
            *(float2*)(C + r1 * Nd + col) = v1;
        }
    }
}

// ================= RoPE (rotation only; q scale applied in flash) =================
__global__ void rope_kernel(float* __restrict__ q, float* __restrict__ k,
                            const float* __restrict__ pos_enc)
{
    const int total = B * N * H * (RD / 2);
    int idx = blockIdx.x * blockDim.x + threadIdx.x;
    if (idx >= total) return;

    const int p = idx % (RD / 2);
    const int h = (idx / (RD / 2)) % H;
    const int n = (idx / ((RD / 2) * H)) % N;
    const int b = idx / ((RD / 2) * H * N);

    const float pe0 = pos_enc[n * RD + 2 * p];
    const float pe1 = pos_enc[n * RD + 2 * p + 1];
    const float c0 = cosf(pe0), s0 = sinf(pe0);
    const float c1 = cosf(pe1), s1 = sinf(pe1);

    const size_t base = ((size_t)(b * N + n)) * D + h * HD + 2 * p;

    float q0 = q[base], q1 = q[base + 1];
    q[base]     = q0 * c0 - q1 * s0;
    q[base + 1] = q1 * c1 + q0 * s1;

    float k0 = k[base], k1 = k[base + 1];
    k[base]     = k0 * c0 - k1 * s0;
    k[base + 1] = k1 * c1 + k0 * s1;
}

// ================= Flash attention (TF32 tensor core, causal) =================
constexpr int FSTR = 72;
constexpr int FLASH_SMEM = (4 * 64 * FSTR) * (int)sizeof(uint32_t) + 64 * (int)sizeof(float);

__global__ __launch_bounds__(128) void flash_tc_kernel(
    const float* __restrict__ q, const float* __restrict__ k,
    const float* __restrict__ v, const unsigned char* __restrict__ pad,
    float* __restrict__ o)
{
    extern __shared__ uint32_t smu[];
    uint32_t* Qs = smu;                    // [64][FSTR]
    uint32_t* Ks = Qs + 64 * FSTR;
    uint32_t* Vs = Ks + 64 * FSTR;
    uint32_t* Ps = Vs + 64 * FSTR;
    float*    Padv = (float*)(Ps + 64 * FSTR);

    const int qt = blockIdx.x;
    const int h  = blockIdx.y;
    const int b  = blockIdx.z;
    const int qi0 = qt * 64;

    const int tid  = threadIdx.x;
    const int wid  = tid >> 5;
    const int lane = tid & 31;
    const int g    = lane >> 2;
    const int tig  = lane & 3;
    const int warp_m = wid * 16;

    const size_t qbase = ((size_t)(b * N + qi0)) * D + h * HD;
    for (int i = tid; i < 64 * 16; i += 128) {
        const int r  = i >> 4;
        const int c4 = (i & 15) * 4;
        float4 qv = *(const float4*)(q + qbase + (size_t)r * D + c4);
        Qs[(c4 + 0) * FSTR + r] = f32_to_tf32(qv.x * 0.125f);
        Qs[(c4 + 1) * FSTR + r] = f32_to_tf32(qv.y * 0.125f);
        Qs[(c4 + 2) * FSTR + r] = f32_to_tf32(qv.z * 0.125f);
        Qs[(c4 + 3) * FSTR + r] = f32_to_tf32(qv.w * 0.125f);
    }

    float m0 = -1e30f, m1 = -1e30f, l0 = 0.0f, l1 = 0.0f;
    float oacc[8][4];
#pragma unroll
    for (int nt = 0; nt < 8; nt++)
#pragma unroll
        for (int r = 0; r < 4; r++) oacc[nt][r] = 0.0f;

    const int ktiles = qt + 1;
    for (int kt = 0; kt < ktiles; kt++) {
        const int kj0 = kt * 64;
        const size_t kbase = ((size_t)(b * N + kj0)) * D + h * HD;

        for (int i = tid; i < 64 * 16; i += 128) {
            const int r  = i >> 4;
            const int c4 = (i & 15) * 4;
            float4 kv = *(const float4*)(k + kbase + (size_t)r * D + c4);
            Ks[(c4 + 0) * FSTR + r] = f32_to_tf32(kv.x);
            Ks[(c4 + 1) * FSTR + r] = f32_to_tf32(kv.y);
            Ks[(c4 + 2) * FSTR + r] = f32_to_tf32(kv.z);
            Ks[(c4 + 3) * FSTR + r] = f32_to_tf32(kv.w);

            float4 vv = *(const float4*)(v + kbase + (size_t)r * D + c4);
            uint4 tv;
            tv.x = f32_to_tf32(vv.x);
            tv.y = f32_to_tf32(vv.y);
            tv.z = f32_to_tf32(vv.z);
            tv.w = f32_to_tf32(vv.w);
            *(uint4*)&Vs[r * FSTR + c4] = tv;
        }
        if (tid < 64)
            Padv[tid] = pad[b * N + kj0 + tid] ? -3e38f : 3e38f;
        __syncthreads();

        float s[8][4];
#pragma unroll
        for (int nt = 0; nt < 8; nt++)
#pragma unroll
            for (int r = 0; r < 4; r++) s[nt][r] = 0.0f;

#pragma unroll
        for (int kk = 0; kk < 64; kk += 8) {
            uint32_t a0 = Qs[(kk + tig    ) * FSTR + warp_m + g    ];
            uint32_t a1 = Qs[(kk + tig    ) * FSTR + warp_m + g + 8];
            uint32_t a2 = Qs[(kk + tig + 4) * FSTR + warp_m + g    ];
            uint32_t a3 = Qs[(kk + tig + 4) * FSTR + warp_m + g + 8];
#pragma unroll
            for (int nt = 0; nt < 8; nt++) {
                uint32_t b0 = Ks[(kk + tig    ) * FSTR + nt * 8 + g];
                uint32_t b1 = Ks[(kk + tig + 4) * FSTR + nt * 8 + g];
                mma_tf32(s[nt][0], s[nt][1], s[nt][2], s[nt][3],
                         a0, a1, a2, a3, b0, b1);
            }
        }

        const int row0 = qi0 + warp_m + g;
        const int row1 = row0 + 8;
#pragma unroll
        for (int nt = 0; nt < 8; nt++) {
            const int c0 = nt * 8 + tig * 2;
            const float p0 = Padv[c0], p1 = Padv[c0 + 1];
            s[nt][0] = fminf(s[nt][0], p0);
            s[nt][1] = fminf(s[nt][1], p1);
            s[nt][2] = fminf(s[nt][2], p0);
            s[nt][3] = fminf(s[nt][3], p1);
        }
        if (kt == qt) {
#pragma unroll
            for (int nt = 0; nt < 8; nt++) {
                const int c0 = kj0 + nt * 8 + tig * 2;
                if (c0     > row0) s[nt][0] = -1e30f;
                if (c0 + 1 > row0) s[nt][1] = -1e30f;
                if (c0     > row1) s[nt][2] = -1e30f;
                if (c0 + 1 > row1) s[nt][3] = -1e30f;
            }
        }

        float mx0 = -1e30f, mx1 = -1e30f;
#pragma unroll
        for (int nt = 0; nt < 8; nt++) {
            mx0 = fmaxf(mx0, fmaxf(s[nt][0], s[nt][1]));
            mx1 = fmaxf(mx1, fmaxf(s[nt][2], s[nt][3]));
        }
        mx0 = fmaxf(mx0, __shfl_xor_sync(0xffffffffu, mx0, 1));
        mx0 = fmaxf(mx0, __shfl_xor_sync(0xffffffffu, mx0, 2));
        mx1 = fmaxf(mx1, __shfl_xor_sync(0xffffffffu, mx1, 1));
        mx1 = fmaxf(mx1, __shfl_xor_sync(0xffffffffu, mx1, 2));

        const float mn0 = fmaxf(m0, mx0);
        const float mn1 = fmaxf(m1, mx1);
        const float al0 = __expf(m0 - mn0);
        const float al1 = __expf(m1 - mn1);
        m0 = mn0; m1 = mn1;

        float sum0 = 0.0f, sum1 = 0.0f;
#pragma unroll
        for (int nt = 0; nt < 8; nt++) {
            s[nt][0] = __expf(s[nt][0] - mn0);
            s[nt][1] = __expf(s[nt][1] - mn0);
            s[nt][2] = __expf(s[nt][2] - mn1);
            s[nt][3] = __expf(s[nt][3] - mn1);
            sum0 += s[nt][0] + s[nt][1];
            sum1 += s[nt][2] + s[nt][3];
        }
        sum0 += __shfl_xor_sync(0xffffffffu, sum0, 1);
        sum0 += __shfl_xor_sync(0xffffffffu, sum0, 2);
        sum1 += __shfl_xor_sync(0xffffffffu, sum1, 1);
        sum1 += __shfl_xor_sync(0xffffffffu, sum1, 2);
        l0 = l0 * al0 + sum0;
        l1 = l1 * al1 + sum1;

#pragma unroll
        for (int nt = 0; nt < 8; nt++) {
#pragma unroll
            for (int r = 0; r < 4; r++) oacc[nt][r] *= (r < 2 ? al0 : al1);
        }

#pragma unroll
        for (int nt = 0; nt < 8; nt++) {
            const int c0 = nt * 8 + tig * 2;
            Ps[(c0    ) * FSTR + warp_m + g    ] = f32_to_tf32(s[nt][0]);
            Ps[(c0 + 1) * FSTR + warp_m + g    ] = f32_to_tf32(s[nt][1]);
            Ps[(c0    ) * FSTR + warp_m + g + 8] = f32_to_tf32(s[nt][2]);
            Ps[(c0 + 1) * FSTR + warp_m + g + 8] = f32_to_tf32(s[nt][3]);
        }
        __syncwarp();

#pragma unroll
        for (int kk = 0; kk < 64; kk += 8) {
            uint32_t a0 = Ps[(kk + tig    ) * FSTR + warp_m + g    ];
            uint32_t a1 = Ps[(kk + tig    ) * FSTR + warp_m + g + 8];
            uint32_t a2 = Ps[(kk + tig + 4) * FSTR + warp_m + g    ];
            uint32_t a3 = Ps[(kk + tig + 4) * FSTR + warp_m + g + 8];
#pragma unroll
            for (int nt = 0; nt < 8; nt++) {
                uint32_t b0 = Vs[(kk + tig    ) * FSTR + nt * 8 + g];
                uint32_t b1 = Vs[(kk + tig + 4) * FSTR + nt * 8 + g];
                mma_tf32(oacc[nt][0], oacc[nt][1], oacc[nt][2], oacc[nt][3],
                         a0, a1, a2, a3, b0, b1);
            }
        }
        __syncthreads();
    }

    const float il0 = 1.0f / l0;
    const float il1 = 1.0f / l1;
    const size_t ob0 = ((size_t)(b * N + qi0 + warp_m + g    )) * D + h * HD;
    const size_t ob1 = ((size_t)(b * N + qi0 + warp_m + g + 8)) * D + h * HD;
#pragma unroll
    for (int nt = 0; nt < 8; nt++) {
        const int c0 = nt * 8 + tig * 2;
        *(float2*)(o + ob0 + c0) = make_float2(oacc[nt][0] * il0, oacc[nt][1] * il0);
        *(float2*)(o + ob1 + c0) = make_float2(oacc[nt][2] * il1, oacc[nt][3] * il1);
    }
}

}  // namespace

extern "C" void kernel_launch(void* const* d_in, const int* in_sizes, int n_in,
                              void* d_out, int out_size)
{
    const float* x_q  = (const float*)d_in[0];
    const float* x_kv = (const float*)d_in[1];
    const float* pos_enc = (const float*)d_in[2];
    const float* Wq = (const float*)d_in[3];
    const float* bq = (const float*)d_in[4];
    const float* Wk = (const float*)d_in[5];
    const float* bk = (const float*)d_in[6];
    const float* Wv = (const float*)d_in[7];
    const float* bv = (const float*)d_in[8];
    const float* Wo = (const float*)d_in[9];
    const float* bo = (const float*)d_in[10];
    const unsigned char* pad = (const unsigned char*)d_in[11];
    float* out = (float*)d_out;

    float *q, *k, *v, *o;
    cudaGetSymbolAddress((void**)&q, g_q);
    cudaGetSymbolAddress((void**)&k, g_k);
    cudaGetSymbolAddress((void**)&v, g_v);
    cudaGetSymbolAddress((void**)&o, g_o);

    const dim3 gemm_grid(D / TBN, M / TBM);  // (8, 64)

    tf32_gemm_bias_kernel<<<gemm_grid, 256>>>(x_q,  Wq, bq, q, D, D);
    tf32_gemm_bias_kernel<<<gemm_grid, 256>>>(x_kv, Wk, bk, k, D, D);
    tf32_gemm_bias_kernel<<<gemm_grid, 256>>>(x_kv, Wv, bv, v, D, D);

    const int rope_total = B * N * H * (RD / 2);
    rope_kernel<<<(rope_total + 255) / 256, 256>>>(q, k, pos_enc);

    cudaFuncSetAttribute(flash_tc_kernel,
                         cudaFuncAttributeMaxDynamicSharedMemorySize, FLASH_SMEM);
    flash_tc_kernel<<<dim3(N / 64, H, B), 128, FLASH_SMEM>>>(q, k, v, pad, o);

    tf32_gemm_bias_kernel<<<gemm_grid, 256>>>(o, Wo, bo, out, D, D);
}

// round 10
// speedup vs baseline: 1.7735x; 1.7735x over previous
#include <cuda_runtime.h>
#include <math.h>
#include <stdint.h>

namespace {

constexpr int B  = 4;
constexpr int N  = 2048;
constexpr int D  = 1024;
constexpr int H  = 16;
constexpr int HD = 64;
constexpr int RD = 32;
constexpr int M  = B * N;   // 8192

// -------- scratch (device globals: allocation-guard safe) --------
__device__ float g_q[M * D];
__device__ float g_k[M * D];
__device__ float g_v[M * D];
__device__ float g_o[M * D];

__device__ __forceinline__ uint32_t f32_to_tf32(float x) {
    uint32_t y;
    asm("cvt.rna.tf32.f32 %0, %1;" : "=r"(y) : "f"(x));
    return y;
}

__device__ __forceinline__ void mma_tf32(
    float& d0, float& d1, float& d2, float& d3,
    uint32_t a0, uint32_t a1, uint32_t a2, uint32_t a3,
    uint32_t b0, uint32_t b1)
{
    asm volatile(
        "mma.sync.aligned.m16n8k8.row.col.f32.tf32.tf32.f32 "
        "{%0,%1,%2,%3}, {%4,%5,%6,%7}, {%8,%9}, {%0,%1,%2,%3};"
        : "+f"(d0), "+f"(d1), "+f"(d2), "+f"(d3)
        : "r"(a0), "r"(a1), "r"(a2), "r"(a3), "r"(b0), "r"(b1));
}

__device__ __forceinline__ void cp_async16(uint32_t smem_addr, const float* gptr) {
    asm volatile("cp.async.cg.shared.global [%0], [%1], 16;"
                 :: "r"(smem_addr), "l"(gptr));
}

// ===== TF32 tensor-core GEMM: 3-stage cp.async pipeline ====================
// 128x128x16 tile, 256 threads (8 warps), warp tile 64x32.
// Smem holds RAW fp32 (cp.async can't convert); cvt.rna.tf32 happens at
// fragment-load time (ALU pipe, hidden under tensor-pipe mmas).
// A staged [m][k] stride 20 (conflict-free frag loads, 16B-aligned chunks);
// B staged [k][n] stride 132.
constexpr int TBM = 128, TBN = 128, TBK = 16;
constexpr int A_STR = 20;                        // floats per A row
constexpr int B_STR = 132;                       // floats per B row
constexpr int A_STAGEF = TBM * A_STR;            // 2560
constexpr int B_STAGEF = TBK * B_STR;            // 2112
constexpr int STAGEF   = A_STAGEF + B_STAGEF;    // 4672 floats
constexpr int GSTAGES  = 3;
constexpr int GEMM_SMEM = GSTAGES * STAGEF * (int)sizeof(float);  // 56064 B

__global__ __launch_bounds__(256, 2) void tf32_gemm_bias_kernel(
    const float* __restrict__ A, const float* __restrict__ W,
    const float* __restrict__ bias, float* __restrict__ C,
    int Nd, int Kd)
{
    extern __shared__ float smf[];
    uint32_t sbase;
    asm("{.reg .u64 t; cvta.to.shared.u64 t, %1; cvt.u32.u64 %0, t;}"
        : "=r"(sbase) : "l"(smf));

    const int tid  = threadIdx.x;
    const int wid  = tid >> 5;
    const int lane = tid & 31;
    const int g    = lane >> 2;
    const int tig  = lane & 3;

    const int warp_m = (wid >> 2) * 64;
    const int warp_n = (wid & 3) * 32;

    const int brow0 = blockIdx.y * TBM;
    const int bcol0 = blockIdx.x * TBN;

    float acc[4][4][4];
#pragma unroll
    for (int mt = 0; mt < 4; mt++)
#pragma unroll
        for (int nt = 0; nt < 4; nt++)
#pragma unroll
            for (int r = 0; r < 4; r++) acc[mt][nt][r] = 0.0f;

    const float* Aptr = A + (size_t)brow0 * Kd;
    const float* Wptr = W + bcol0;

    // loader mapping (per thread: 2 A-float4, 2 B-float4 per tile)
    const int aRow0 = tid >> 2;            // 0..63
    const int aRow1 = aRow0 + 64;          // 64..127
    const int aCol  = (tid & 3) * 4;       // 0,4,8,12
    const int bRow0 = tid >> 5;            // 0..7
    const int bRow1 = bRow0 + 8;           // 8..15
    const int bCol  = (tid & 31) * 4;      // 0..124

    const int NT = Kd / TBK;               // 64

    auto issue_tile = [&](int t) {
        const int kt = t * TBK;
        const uint32_t ab = sbase + (uint32_t)((t % GSTAGES) * STAGEF) * 4u;
        const uint32_t bb = ab + (uint32_t)A_STAGEF * 4u;
        cp_async16(ab + (uint32_t)(aRow0 * A_STR + aCol) * 4u,
                   Aptr + (size_t)aRow0 * Kd + kt + aCol);
        cp_async16(ab + (uint32_t)(aRow1 * A_STR + aCol) * 4u,
                   Aptr + (size_t)aRow1 * Kd + kt + aCol);
        cp_async16(bb + (uint32_t)(bRow0 * B_STR + bCol) * 4u,
                   Wptr + (size_t)(kt + bRow0) * Nd + bCol);
        cp_async16(bb + (uint32_t)(bRow1 * B_STR + bCol) * 4u,
                   Wptr + (size_t)(kt + bRow1) * Nd + bCol);
        asm volatile("cp.async.commit_group;" ::: "memory");
    };

    issue_tile(0);
    issue_tile(1);

    for (int t = 0; t < NT; t++) {
        if (t == NT - 1)
            asm volatile("cp.async.wait_group 0;" ::: "memory");
        else
            asm volatile("cp.async.wait_group 1;" ::: "memory");
        __syncthreads();

        const float* Af = smf + (t % GSTAGES) * STAGEF;
        const float* Bf = Af + A_STAGEF;

#pragma unroll
        for (int kk = 0; kk < TBK; kk += 8) {
            uint32_t af[4][4], bf[4][2];
#pragma unroll
            for (int mt = 0; mt < 4; mt++) {
                const int rm = warp_m + mt * 16;
                af[mt][0] = f32_to_tf32(Af[(rm + g    ) * A_STR + kk + tig    ]);
                af[mt][1] = f32_to_tf32(Af[(rm + g + 8) * A_STR + kk + tig    ]);
                af[mt][2] = f32_to_tf32(Af[(rm + g    ) * A_STR + kk + tig + 4]);
                af[mt][3] = f32_to_tf32(Af[(rm + g + 8) * A_STR + kk + tig + 4]);
            }
#pragma unroll
            for (int nt = 0; nt < 4; nt++) {
                const int cn = warp_n + nt * 8;
                bf[nt][0] = f32_to_tf32(Bf[(kk + tig    ) * B_STR + cn + g]);
                bf[nt][1] = f32_to_tf32(Bf[(kk + tig + 4) * B_STR + cn + g]);
            }
#pragma unroll
            for (int mt = 0; mt < 4; mt++)
#pragma unroll
                for (int nt = 0; nt < 4; nt++)
                    mma_tf32(acc[mt][nt][0], acc[mt][nt][1],
                             acc[mt][nt][2], acc[mt][nt][3],
                             af[mt][0], af[mt][1], af[mt][2], af[mt][3],
                             bf[nt][0], bf[nt][1]);
        }

        if (t + 2 < NT) issue_tile(t + 2);
    }

    // epilogue: bias + store
#pragma unroll
    for (int mt = 0; mt < 4; mt++) {
#pragma unroll
        for (int nt = 0; nt < 4; nt++) {
            const int col = bcol0 + warp_n + nt * 8 + tig * 2;
            const float b0 = bias[col], b1 = bias[col + 1];
            const size_t r0 = (size_t)(brow0 + warp_m + mt * 16 + g);
            const size_t r1 = r0 + 8;
            float2 v0 = make_float2(acc[mt][nt][0] + b0, acc[mt][nt][1] + b1);
            float2 v1 = make_float2(acc[mt][nt][2] + b0, acc[mt][nt][3] + b1);
            *(float2*)(C + r0 * Nd + col) = v0;
            *(float2*)(C + r1 * Nd + col) = v1;
        }
    }
}

// ================= RoPE (rotation only; q scale applied in flash) =================
__global__ void rope_kernel(float* __restrict__ q, float* __restrict__ k,
                            const float* __restrict__ pos_enc)
{
    const int total = B * N * H * (RD / 2);
    int idx = blockIdx.x * blockDim.x + threadIdx.x;
    if (idx >= total) return;

    const int p = idx % (RD / 2);
    const int h = (idx / (RD / 2)) % H;
    const int n = (idx / ((RD / 2) * H)) % N;
    const int b = idx / ((RD / 2) * H * N);

    const float pe0 = pos_enc[n * RD + 2 * p];
    const float pe1 = pos_enc[n * RD + 2 * p + 1];
    const float c0 = cosf(pe0), s0 = sinf(pe0);
    const float c1 = cosf(pe1), s1 = sinf(pe1);

    const size_t base = ((size_t)(b * N + n)) * D + h * HD + 2 * p;

    float q0 = q[base], q1 = q[base + 1];
    q[base]     = q0 * c0 - q1 * s0;
    q[base + 1] = q1 * c1 + q0 * s1;

    float k0 = k[base], k1 = k[base + 1];
    k[base]     = k0 * c0 - k1 * s0;
    k[base + 1] = k1 * c1 + k0 * s1;
}

// ================= Flash attention (TF32 tensor core, causal) =================
constexpr int FSTR = 72;
constexpr int FLASH_SMEM = (4 * 64 * FSTR) * (int)sizeof(uint32_t) + 64 * (int)sizeof(float);

__global__ __launch_bounds__(128) void flash_tc_kernel(
    const float* __restrict__ q, const float* __restrict__ k,
    const float* __restrict__ v, const unsigned char* __restrict__ pad,
    float* __restrict__ o)
{
    extern __shared__ uint32_t smu[];
    uint32_t* Qs = smu;                    // [64][FSTR]
    uint32_t* Ks = Qs + 64 * FSTR;
    uint32_t* Vs = Ks + 64 * FSTR;
    uint32_t* Ps = Vs + 64 * FSTR;
    float*    Padv = (float*)(Ps + 64 * FSTR);

    const int qt = blockIdx.x;
    const int h  = blockIdx.y;
    const int b  = blockIdx.z;
    const int qi0 = qt * 64;

    const int tid  = threadIdx.x;
    const int wid  = tid >> 5;
    const int lane = tid & 31;
    const int g    = lane >> 2;
    const int tig  = lane & 3;
    const int warp_m = wid * 16;

    const size_t qbase = ((size_t)(b * N + qi0)) * D + h * HD;
    for (int i = tid; i < 64 * 16; i += 128) {
        const int r  = i >> 4;
        const int c4 = (i & 15) * 4;
        float4 qv = *(const float4*)(q + qbase + (size_t)r * D + c4);
        Qs[(c4 + 0) * FSTR + r] = f32_to_tf32(qv.x * 0.125f);
        Qs[(c4 + 1) * FSTR + r] = f32_to_tf32(qv.y * 0.125f);
        Qs[(c4 + 2) * FSTR + r] = f32_to_tf32(qv.z * 0.125f);
        Qs[(c4 + 3) * FSTR + r] = f32_to_tf32(qv.w * 0.125f);
    }

    float m0 = -1e30f, m1 = -1e30f, l0 = 0.0f, l1 = 0.0f;
    float oacc[8][4];
#pragma unroll
    for (int nt = 0; nt < 8; nt++)
#pragma unroll
        for (int r = 0; r < 4; r++) oacc[nt][r] = 0.0f;

    const int ktiles = qt + 1;
    for (int kt = 0; kt < ktiles; kt++) {
        const int kj0 = kt * 64;
        const size_t kbase = ((size_t)(b * N + kj0)) * D + h * HD;

        for (int i = tid; i < 64 * 16; i += 128) {
            const int r  = i >> 4;
            const int c4 = (i & 15) * 4;
            float4 kv = *(const float4*)(k + kbase + (size_t)r * D + c4);
            Ks[(c4 + 0) * FSTR + r] = f32_to_tf32(kv.x);
            Ks[(c4 + 1) * FSTR + r] = f32_to_tf32(kv.y);
            Ks[(c4 + 2) * FSTR + r] = f32_to_tf32(kv.z);
            Ks[(c4 + 3) * FSTR + r] = f32_to_tf32(kv.w);

            float4 vv = *(const float4*)(v + kbase + (size_t)r * D + c4);
            uint4 tv;
            tv.x = f32_to_tf32(vv.x);
            tv.y = f32_to_tf32(vv.y);
            tv.z = f32_to_tf32(vv.z);
            tv.w = f32_to_tf32(vv.w);
            *(uint4*)&Vs[r * FSTR + c4] = tv;
        }
        if (tid < 64)
            Padv[tid] = pad[b * N + kj0 + tid] ? -3e38f : 3e38f;
        __syncthreads();

        float s[8][4];
#pragma unroll
        for (int nt = 0; nt < 8; nt++)
#pragma unroll
            for (int r = 0; r < 4; r++) s[nt][r] = 0.0f;

#pragma unroll
        for (int kk = 0; kk < 64; kk += 8) {
            uint32_t a0 = Qs[(kk + tig    ) * FSTR + warp_m + g    ];
            uint32_t a1 = Qs[(kk + tig    ) * FSTR + warp_m + g + 8];
            uint32_t a2 = Qs[(kk + tig + 4) * FSTR + warp_m + g    ];
            uint32_t a3 = Qs[(kk + tig + 4) * FSTR + warp_m + g + 8];
#pragma unroll
            for (int nt = 0; nt < 8; nt++) {
                uint32_t b0 = Ks[(kk + tig    ) * FSTR + nt * 8 + g];
                uint32_t b1 = Ks[(kk + tig + 4) * FSTR + nt * 8 + g];
                mma_tf32(s[nt][0], s[nt][1], s[nt][2], s[nt][3],
                         a0, a1, a2, a3, b0, b1);
            }
        }

        const int row0 = qi0 + warp_m + g;
        const int row1 = row0 + 8;
#pragma unroll
        for (int nt = 0; nt < 8; nt++) {
            const int c0 = nt * 8 + tig * 2;
            const float p0 = Padv[c0], p1 = Padv[c0 + 1];
            s[nt][0] = fminf(s[nt][0], p0);
            s[nt][1] = fminf(s[nt][1], p1);
            s[nt][2] = fminf(s[nt][2], p0);
            s[nt][3] = fminf(s[nt][3], p1);
        }
        if (kt == qt) {
#pragma unroll
            for (int nt = 0; nt < 8; nt++) {
                const int c0 = kj0 + nt * 8 + tig * 2;
                if (c0     > row0) s[nt][0] = -1e30f;
                if (c0 + 1 > row0) s[nt][1] = -1e30f;
                if (c0     > row1) s[nt][2] = -1e30f;
                if (c0 + 1 > row1) s[nt][3] = -1e30f;
            }
        }

        float mx0 = -1e30f, mx1 = -1e30f;
#pragma unroll
        for (int nt = 0; nt < 8; nt++) {
            mx0 = fmaxf(mx0, fmaxf(s[nt][0], s[nt][1]));
            mx1 = fmaxf(mx1, fmaxf(s[nt][2], s[nt][3]));
        }
        mx0 = fmaxf(mx0, __shfl_xor_sync(0xffffffffu, mx0, 1));
        mx0 = fmaxf(mx0, __shfl_xor_sync(0xffffffffu, mx0, 2));
        mx1 = fmaxf(mx1, __shfl_xor_sync(0xffffffffu, mx1, 1));
        mx1 = fmaxf(mx1, __shfl_xor_sync(0xffffffffu, mx1, 2));

        const float mn0 = fmaxf(m0, mx0);
        const float mn1 = fmaxf(m1, mx1);
        const float al0 = __expf(m0 - mn0);
        const float al1 = __expf(m1 - mn1);
        m0 = mn0; m1 = mn1;

        float sum0 = 0.0f, sum1 = 0.0f;
#pragma unroll
        for (int nt = 0; nt < 8; nt++) {
            s[nt][0] = __expf(s[nt][0] - mn0);
            s[nt][1] = __expf(s[nt][1] - mn0);
            s[nt][2] = __expf(s[nt][2] - mn1);
            s[nt][3] = __expf(s[nt][3] - mn1);
            sum0 += s[nt][0] + s[nt][1];
            sum1 += s[nt][2] + s[nt][3];
        }
        sum0 += __shfl_xor_sync(0xffffffffu, sum0, 1);
        sum0 += __shfl_xor_sync(0xffffffffu, sum0, 2);
        sum1 += __shfl_xor_sync(0xffffffffu, sum1, 1);
        sum1 += __shfl_xor_sync(0xffffffffu, sum1, 2);
        l0 = l0 * al0 + sum0;
        l1 = l1 * al1 + sum1;

#pragma unroll
        for (int nt = 0; nt < 8; nt++) {
#pragma unroll
            for (int r = 0; r < 4; r++) oacc[nt][r] *= (r < 2 ? al0 : al1);
        }

#pragma unroll
        for (int nt = 0; nt < 8; nt++) {
            const int c0 = nt * 8 + tig * 2;
            Ps[(c0    ) * FSTR + warp_m + g    ] = f32_to_tf32(s[nt][0]);
            Ps[(c0 + 1) * FSTR + warp_m + g    ] = f32_to_tf32(s[nt][1]);
            Ps[(c0    ) * FSTR + warp_m + g + 8] = f32_to_tf32(s[nt][2]);
            Ps[(c0 + 1) * FSTR + warp_m + g + 8] = f32_to_tf32(s[nt][3]);
        }
        __syncwarp();

#pragma unroll
        for (int kk = 0; kk < 64; kk += 8) {
            uint32_t a0 = Ps[(kk + tig    ) * FSTR + warp_m + g    ];
            uint32_t a1 = Ps[(kk + tig    ) * FSTR + warp_m + g + 8];
            uint32_t a2 = Ps[(kk + tig + 4) * FSTR + warp_m + g    ];
            uint32_t a3 = Ps[(kk + tig + 4) * FSTR + warp_m + g + 8];
#pragma unroll
            for (int nt = 0; nt < 8; nt++) {
                uint32_t b0 = Vs[(kk + tig    ) * FSTR + nt * 8 + g];
                uint32_t b1 = Vs[(kk + tig + 4) * FSTR + nt * 8 + g];
                mma_tf32(oacc[nt][0], oacc[nt][1], oacc[nt][2], oacc[nt][3],
                         a0, a1, a2, a3, b0, b1);
            }
        }
        __syncthreads();
    }

    const float il0 = 1.0f / l0;
    const float il1 = 1.0f / l1;
    const size_t ob0 = ((size_t)(b * N + qi0 + warp_m + g    )) * D + h * HD;
    const size_t ob1 = ((size_t)(b * N + qi0 + warp_m + g + 8)) * D + h * HD;
#pragma unroll
    for (int nt = 0; nt < 8; nt++) {
        const int c0 = nt * 8 + tig * 2;
        *(float2*)(o + ob0 + c0) = make_float2(oacc[nt][0] * il0, oacc[nt][1] * il0);
        *(float2*)(o + ob1 + c0) = make_float2(oacc[nt][2] * il1, oacc[nt][3] * il1);
    }
}

}  // namespace

extern "C" void kernel_launch(void* const* d_in, const int* in_sizes, int n_in,
                              void* d_out, int out_size)
{
    const float* x_q  = (const float*)d_in[0];
    const float* x_kv = (const float*)d_in[1];
    const float* pos_enc = (const float*)d_in[2];
    const float* Wq = (const float*)d_in[3];
    const float* bq = (const float*)d_in[4];
    const float* Wk = (const float*)d_in[5];
    const float* bk = (const float*)d_in[6];
    const float* Wv = (const float*)d_in[7];
    const float* bv = (const float*)d_in[8];
    const float* Wo = (const float*)d_in[9];
    const float* bo = (const float*)d_in[10];
    const unsigned char* pad = (const unsigned char*)d_in[11];
    float* out = (float*)d_out;

    float *q, *k, *v, *o;
    cudaGetSymbolAddress((void**)&q, g_q);
    cudaGetSymbolAddress((void**)&k, g_k);
    cudaGetSymbolAddress((void**)&v, g_v);
    cudaGetSymbolAddress((void**)&o, g_o);

    const dim3 gemm_grid(D / TBN, M / TBM);  // (8, 64)

    cudaFuncSetAttribute(tf32_gemm_bias_kernel,
                         cudaFuncAttributeMaxDynamicSharedMemorySize, GEMM_SMEM);

    tf32_gemm_bias_kernel<<<gemm_grid, 256, GEMM_SMEM>>>(x_q,  Wq, bq, q, D, D);
    tf32_gemm_bias_kernel<<<gemm_grid, 256, GEMM_SMEM>>>(x_kv, Wk, bk, k, D, D);
    tf32_gemm_bias_kernel<<<gemm_grid, 256, GEMM_SMEM>>>(x_kv, Wv, bv, v, D, D);

    const int rope_total = B * N * H * (RD / 2);
    rope_kernel<<<(rope_total + 255) / 256, 256>>>(q, k, pos_enc);

    cudaFuncSetAttribute(flash_tc_kernel,
                         cudaFuncAttributeMaxDynamicSharedMemorySize, FLASH_SMEM);
    flash_tc_kernel<<<dim3(N / 64, H, B), 128, FLASH_SMEM>>>(q, k, v, pad, o);

    tf32_gemm_bias_kernel<<<gemm_grid, 256, GEMM_SMEM>>>(o, Wo, bo, out, D, D);
}

// round 11
// speedup vs baseline: 2.1919x; 1.2359x over previous
#include <cuda_runtime.h>
#include <math.h>
#include <stdint.h>

namespace {

constexpr int B  = 4;
constexpr int N  = 2048;
constexpr int D  = 1024;
constexpr int H  = 16;
constexpr int HD = 64;
constexpr int RD = 32;
constexpr int M  = B * N;   // 8192

// -------- scratch (device globals: allocation-guard safe) --------
__device__ float g_q[M * D];
__device__ float g_k[M * D];
__device__ float g_v[M * D];
__device__ float g_o[M * D];

__device__ __forceinline__ uint32_t f32_to_tf32(float x) {
    uint32_t y;
    asm("cvt.rna.tf32.f32 %0, %1;" : "=r"(y) : "f"(x));
    return y;
}

__device__ __forceinline__ void mma_tf32(
    float& d0, float& d1, float& d2, float& d3,
    uint32_t a0, uint32_t a1, uint32_t a2, uint32_t a3,
    uint32_t b0, uint32_t b1)
{
    asm volatile(
        "mma.sync.aligned.m16n8k8.row.col.f32.tf32.tf32.f32 "
        "{%0,%1,%2,%3}, {%4,%5,%6,%7}, {%8,%9}, {%0,%1,%2,%3};"
        : "+f"(d0), "+f"(d1), "+f"(d2), "+f"(d3)
        : "r"(a0), "r"(a1), "r"(a2), "r"(a3), "r"(b0), "r"(b1));
}

__device__ __forceinline__ void cp_async16(uint32_t smem_addr, const float* gptr) {
    asm volatile("cp.async.cg.shared.global [%0], [%1], 16;"
                 :: "r"(smem_addr), "l"(gptr));
}

// ===== TF32 tensor-core GEMM: 3-stage cp.async pipeline (unchanged, R10) ===
constexpr int TBM = 128, TBN = 128, TBK = 16;
constexpr int A_STR = 20;
constexpr int B_STR = 132;
constexpr int A_STAGEF = TBM * A_STR;            // 2560
constexpr int B_STAGEF = TBK * B_STR;            // 2112
constexpr int STAGEF   = A_STAGEF + B_STAGEF;    // 4672 floats
constexpr int GSTAGES  = 3;
constexpr int GEMM_SMEM = GSTAGES * STAGEF * (int)sizeof(float);  // 56064 B

__global__ __launch_bounds__(256, 2) void tf32_gemm_bias_kernel(
    const float* __restrict__ A, const float* __restrict__ W,
    const float* __restrict__ bias, float* __restrict__ C,
    int Nd, int Kd)
{
    extern __shared__ float smf[];
    uint32_t sbase;
    asm("{.reg .u64 t; cvta.to.shared.u64 t, %1; cvt.u32.u64 %0, t;}"
        : "=r"(sbase) : "l"(smf));

    const int tid  = threadIdx.x;
    const int wid  = tid >> 5;
    const int lane = tid & 31;
    const int g    = lane >> 2;
    const int tig  = lane & 3;

    const int warp_m = (wid >> 2) * 64;
    const int warp_n = (wid & 3) * 32;

    const int brow0 = blockIdx.y * TBM;
    const int bcol0 = blockIdx.x * TBN;

    float acc[4][4][4];
#pragma unroll
    for (int mt = 0; mt < 4; mt++)
#pragma unroll
        for (int nt = 0; nt < 4; nt++)
#pragma unroll
            for (int r = 0; r < 4; r++) acc[mt][nt][r] = 0.0f;

    const float* Aptr = A + (size_t)brow0 * Kd;
    const float* Wptr = W + bcol0;

    const int aRow0 = tid >> 2;
    const int aRow1 = aRow0 + 64;
    const int aCol  = (tid & 3) * 4;
    const int bRow0 = tid >> 5;
    const int bRow1 = bRow0 + 8;
    const int bCol  = (tid & 31) * 4;

    const int NT = Kd / TBK;

    auto issue_tile = [&](int t) {
        const int kt = t * TBK;
        const uint32_t ab = sbase + (uint32_t)((t % GSTAGES) * STAGEF) * 4u;
        const uint32_t bb = ab + (uint32_t)A_STAGEF * 4u;
        cp_async16(ab + (uint32_t)(aRow0 * A_STR + aCol) * 4u,
                   Aptr + (size_t)aRow0 * Kd + kt + aCol);
        cp_async16(ab + (uint32_t)(aRow1 * A_STR + aCol) * 4u,
                   Aptr + (size_t)aRow1 * Kd + kt + aCol);
        cp_async16(bb + (uint32_t)(bRow0 * B_STR + bCol) * 4u,
                   Wptr + (size_t)(kt + bRow0) * Nd + bCol);
        cp_async16(bb + (uint32_t)(bRow1 * B_STR + bCol) * 4u,
                   Wptr + (size_t)(kt + bRow1) * Nd + bCol);
        asm volatile("cp.async.commit_group;" ::: "memory");
    };

    issue_tile(0);
    issue_tile(1);

    for (int t = 0; t < NT; t++) {
        if (t == NT - 1)
            asm volatile("cp.async.wait_group 0;" ::: "memory");
        else
            asm volatile("cp.async.wait_group 1;" ::: "memory");
        __syncthreads();

        const float* Af = smf + (t % GSTAGES) * STAGEF;
        const float* Bf = Af + A_STAGEF;

#pragma unroll
        for (int kk = 0; kk < TBK; kk += 8) {
            uint32_t af[4][4], bf[4][2];
#pragma unroll
            for (int mt = 0; mt < 4; mt++) {
                const int rm = warp_m + mt * 16;
                af[mt][0] = f32_to_tf32(Af[(rm + g    ) * A_STR + kk + tig    ]);
                af[mt][1] = f32_to_tf32(Af[(rm + g + 8) * A_STR + kk + tig    ]);
                af[mt][2] = f32_to_tf32(Af[(rm + g    ) * A_STR + kk + tig + 4]);
                af[mt][3] = f32_to_tf32(Af[(rm + g + 8) * A_STR + kk + tig + 4]);
            }
#pragma unroll
            for (int nt = 0; nt < 4; nt++) {
                const int cn = warp_n + nt * 8;
                bf[nt][0] = f32_to_tf32(Bf[(kk + tig    ) * B_STR + cn + g]);
                bf[nt][1] = f32_to_tf32(Bf[(kk + tig + 4) * B_STR + cn + g]);
            }
#pragma unroll
            for (int mt = 0; mt < 4; mt++)
#pragma unroll
                for (int nt = 0; nt < 4; nt++)
                    mma_tf32(acc[mt][nt][0], acc[mt][nt][1],
                             acc[mt][nt][2], acc[mt][nt][3],
                             af[mt][0], af[mt][1], af[mt][2], af[mt][3],
                             bf[nt][0], bf[nt][1]);
        }

        if (t + 2 < NT) issue_tile(t + 2);
    }

#pragma unroll
    for (int mt = 0; mt < 4; mt++) {
#pragma unroll
        for (int nt = 0; nt < 4; nt++) {
            const int col = bcol0 + warp_n + nt * 8 + tig * 2;
            const float b0 = bias[col], b1 = bias[col + 1];
            const size_t r0 = (size_t)(brow0 + warp_m + mt * 16 + g);
            const size_t r1 = r0 + 8;
            float2 v0 = make_float2(acc[mt][nt][0] + b0, acc[mt][nt][1] + b1);
            float2 v1 = make_float2(acc[mt][nt][2] + b0, acc[mt][nt][3] + b1);
            *(float2*)(C + r0 * Nd + col) = v0;
            *(float2*)(C + r1 * Nd + col) = v1;
        }
    }
}

// ================= RoPE (rotation only; q scale applied in flash) =================
__global__ void rope_kernel(float* __restrict__ q, float* __restrict__ k,
                            const float* __restrict__ pos_enc)
{
    const int total = B * N * H * (RD / 2);
    int idx = blockIdx.x * blockDim.x + threadIdx.x;
    if (idx >= total) return;

    const int p = idx % (RD / 2);
    const int h = (idx / (RD / 2)) % H;
    const int n = (idx / ((RD / 2) * H)) % N;
    const int b = idx / ((RD / 2) * H * N);

    const float pe0 = pos_enc[n * RD + 2 * p];
    const float pe1 = pos_enc[n * RD + 2 * p + 1];
    const float c0 = cosf(pe0), s0 = sinf(pe0);
    const float c1 = cosf(pe1), s1 = sinf(pe1);

    const size_t base = ((size_t)(b * N + n)) * D + h * HD + 2 * p;

    float q0 = q[base], q1 = q[base + 1];
    q[base]     = q0 * c0 - q1 * s0;
    q[base + 1] = q1 * c1 + q0 * s1;

    float k0 = k[base], k1 = k[base + 1];
    k[base]     = k0 * c0 - k1 * s0;
    k[base + 1] = k1 * c1 + k0 * s1;
}

// ===== Flash attention (TF32 TC) with cp.async double-buffered K/V =========
// 64x64 tiles, 4 warps. Smem (word offsets):
//   Qs  [0,4608)        tf32 [d][row]    stride 72 (A-frag QK, conflict-free)
//   Ps  [4608,9216)     tf32 [key][row]  stride 72 (A-frag PV)
//   Kf  [9216,+2*4352)  fp32 [key][d]    stride 68, 2 stages (B-frag QK: 4g+tig banks, CF)
//   Vf  [17920,+2*4608) fp32 [key][d]    stride 72, 2 stages (B-frag PV: 8tig+g banks, CF)
//   Pad [27136,+128)    2 stages of 64 floats
constexpr int FSTR   = 72;
constexpr int KSTR   = 68;
constexpr int QS_OFF  = 0;
constexpr int PS_OFF  = 64 * FSTR;                 // 4608
constexpr int KF_OFF  = PS_OFF + 64 * FSTR;        // 9216
constexpr int KSTAGE  = 64 * KSTR;                 // 4352
constexpr int VF_OFF  = KF_OFF + 2 * KSTAGE;       // 17920
constexpr int VSTAGE  = 64 * FSTR;                 // 4608
constexpr int PAD_OFF = VF_OFF + 2 * VSTAGE;       // 27136
constexpr int FLASH_SMEM = (PAD_OFF + 128) * (int)sizeof(uint32_t);  // 109056 B

__global__ __launch_bounds__(128) void flash_tc_kernel(
    const float* __restrict__ q, const float* __restrict__ k,
    const float* __restrict__ v, const unsigned char* __restrict__ pad,
    float* __restrict__ o)
{
    extern __shared__ uint32_t smu[];
    uint32_t sbase;
    asm("{.reg .u64 t; cvta.to.shared.u64 t, %1; cvt.u32.u64 %0, t;}"
        : "=r"(sbase) : "l"(smu));

    uint32_t* Qs   = smu + QS_OFF;
    uint32_t* Ps   = smu + PS_OFF;
    float*    Padv = (float*)(smu + PAD_OFF);

    const int qt = blockIdx.x;
    const int h  = blockIdx.y;
    const int b  = blockIdx.z;
    const int qi0 = qt * 64;

    const int tid  = threadIdx.x;
    const int wid  = tid >> 5;
    const int lane = tid & 31;
    const int g    = lane >> 2;
    const int tig  = lane & 3;
    const int warp_m = wid * 16;

    // issue cp.async for K/V tile t into stage t&1 (+ pad mask, regular STS)
    auto issue_kv = [&](int t) {
        const int kj0 = t * 64;
        const size_t kb = ((size_t)(b * N + kj0)) * D + h * HD;
        const uint32_t kbuf = sbase + (uint32_t)(KF_OFF + (t & 1) * KSTAGE) * 4u;
        const uint32_t vbuf = sbase + (uint32_t)(VF_OFF + (t & 1) * VSTAGE) * 4u;
        for (int i = tid; i < 64 * 16; i += 128) {
            const int r  = i >> 4;
            const int c4 = (i & 15) * 4;
            cp_async16(kbuf + (uint32_t)(r * KSTR + c4) * 4u, k + kb + (size_t)r * D + c4);
            cp_async16(vbuf + (uint32_t)(r * FSTR + c4) * 4u, v + kb + (size_t)r * D + c4);
        }
        asm volatile("cp.async.commit_group;" ::: "memory");
        if (tid < 64)
            Padv[(t & 1) * 64 + tid] = pad[b * N + kj0 + tid] ? -3e38f : 3e38f;
    };

    issue_kv(0);

    // ---- load Q tile (scaled), transposed into Qs[d][row] (tf32) ----
    const size_t qbase = ((size_t)(b * N + qi0)) * D + h * HD;
    for (int i = tid; i < 64 * 16; i += 128) {
        const int r  = i >> 4;
        const int c4 = (i & 15) * 4;
        float4 qv = *(const float4*)(q + qbase + (size_t)r * D + c4);
        Qs[(c4 + 0) * FSTR + r] = f32_to_tf32(qv.x * 0.125f);
        Qs[(c4 + 1) * FSTR + r] = f32_to_tf32(qv.y * 0.125f);
        Qs[(c4 + 2) * FSTR + r] = f32_to_tf32(qv.z * 0.125f);
        Qs[(c4 + 3) * FSTR + r] = f32_to_tf32(qv.w * 0.125f);
    }

    float m0 = -1e30f, m1 = -1e30f, l0 = 0.0f, l1 = 0.0f;
    float oacc[8][4];
#pragma unroll
    for (int nt = 0; nt < 8; nt++)
#pragma unroll
        for (int r = 0; r < 4; r++) oacc[nt][r] = 0.0f;

    const int ktiles = qt + 1;
    for (int kt = 0; kt < ktiles; kt++) {
        const bool have_next = (kt + 1) < ktiles;
        if (have_next) {
            issue_kv(kt + 1);
            asm volatile("cp.async.wait_group 1;" ::: "memory");
        } else {
            asm volatile("cp.async.wait_group 0;" ::: "memory");
        }
        __syncthreads();   // K/V/pad of tile kt visible to all warps

        const float* Kf = (const float*)(smu + KF_OFF + (kt & 1) * KSTAGE);
        const float* Vf = (const float*)(smu + VF_OFF + (kt & 1) * VSTAGE);
        const float* Pv = Padv + (kt & 1) * 64;

        // ---- S = Q K^T ----
        float s[8][4];
#pragma unroll
        for (int nt = 0; nt < 8; nt++)
#pragma unroll
            for (int r = 0; r < 4; r++) s[nt][r] = 0.0f;

#pragma unroll
        for (int kk = 0; kk < 64; kk += 8) {
            uint32_t a0 = Qs[(kk + tig    ) * FSTR + warp_m + g    ];
            uint32_t a1 = Qs[(kk + tig    ) * FSTR + warp_m + g + 8];
            uint32_t a2 = Qs[(kk + tig + 4) * FSTR + warp_m + g    ];
            uint32_t a3 = Qs[(kk + tig + 4) * FSTR + warp_m + g + 8];
#pragma unroll
            for (int nt = 0; nt < 8; nt++) {
                uint32_t b0 = f32_to_tf32(Kf[(nt * 8 + g) * KSTR + kk + tig    ]);
                uint32_t b1 = f32_to_tf32(Kf[(nt * 8 + g) * KSTR + kk + tig + 4]);
                mma_tf32(s[nt][0], s[nt][1], s[nt][2], s[nt][3],
                         a0, a1, a2, a3, b0, b1);
            }
        }

        // ---- mask ----
        const int kj0 = kt * 64;
        const int row0 = qi0 + warp_m + g;
        const int row1 = row0 + 8;
#pragma unroll
        for (int nt = 0; nt < 8; nt++) {
            const int c0 = nt * 8 + tig * 2;
            const float p0 = Pv[c0], p1 = Pv[c0 + 1];
            s[nt][0] = fminf(s[nt][0], p0);
            s[nt][1] = fminf(s[nt][1], p1);
            s[nt][2] = fminf(s[nt][2], p0);
            s[nt][3] = fminf(s[nt][3], p1);
        }
        if (kt == qt) {
#pragma unroll
            for (int nt = 0; nt < 8; nt++) {
                const int c0 = kj0 + nt * 8 + tig * 2;
                if (c0     > row0) s[nt][0] = -1e30f;
                if (c0 + 1 > row0) s[nt][1] = -1e30f;
                if (c0     > row1) s[nt][2] = -1e30f;
                if (c0 + 1 > row1) s[nt][3] = -1e30f;
            }
        }

        // ---- online softmax ----
        float mx0 = -1e30f, mx1 = -1e30f;
#pragma unroll
        for (int nt = 0; nt < 8; nt++) {
            mx0 = fmaxf(mx0, fmaxf(s[nt][0], s[nt][1]));
            mx1 = fmaxf(mx1, fmaxf(s[nt][2], s[nt][3]));
        }
        mx0 = fmaxf(mx0, __shfl_xor_sync(0xffffffffu, mx0, 1));
        mx0 = fmaxf(mx0, __shfl_xor_sync(0xffffffffu, mx0, 2));
        mx1 = fmaxf(mx1, __shfl_xor_sync(0xffffffffu, mx1, 1));
        mx1 = fmaxf(mx1, __shfl_xor_sync(0xffffffffu, mx1, 2));

        const float mn0 = fmaxf(m0, mx0);
        const float mn1 = fmaxf(m1, mx1);
        const float al0 = __expf(m0 - mn0);
        const float al1 = __expf(m1 - mn1);
        m0 = mn0; m1 = mn1;

        float sum0 = 0.0f, sum1 = 0.0f;
#pragma unroll
        for (int nt = 0; nt < 8; nt++) {
            s[nt][0] = __expf(s[nt][0] - mn0);
            s[nt][1] = __expf(s[nt][1] - mn0);
            s[nt][2] = __expf(s[nt][2] - mn1);
            s[nt][3] = __expf(s[nt][3] - mn1);
            sum0 += s[nt][0] + s[nt][1];
            sum1 += s[nt][2] + s[nt][3];
        }
        sum0 += __shfl_xor_sync(0xffffffffu, sum0, 1);
        sum0 += __shfl_xor_sync(0xffffffffu, sum0, 2);
        sum1 += __shfl_xor_sync(0xffffffffu, sum1, 1);
        sum1 += __shfl_xor_sync(0xffffffffu, sum1, 2);
        l0 = l0 * al0 + sum0;
        l1 = l1 * al1 + sum1;

#pragma unroll
        for (int nt = 0; nt < 8; nt++) {
#pragma unroll
            for (int r = 0; r < 4; r++) oacc[nt][r] *= (r < 2 ? al0 : al1);
        }

        // ---- P -> smem (tf32 [key][row]) ----
#pragma unroll
        for (int nt = 0; nt < 8; nt++) {
            const int c0 = nt * 8 + tig * 2;
            Ps[(c0    ) * FSTR + warp_m + g    ] = f32_to_tf32(s[nt][0]);
            Ps[(c0 + 1) * FSTR + warp_m + g    ] = f32_to_tf32(s[nt][1]);
            Ps[(c0    ) * FSTR + warp_m + g + 8] = f32_to_tf32(s[nt][2]);
            Ps[(c0 + 1) * FSTR + warp_m + g + 8] = f32_to_tf32(s[nt][3]);
        }
        __syncwarp();   // Ps rows warp-private

        // ---- O += P V ----
#pragma unroll
        for (int kk = 0; kk < 64; kk += 8) {
            uint32_t a0 = Ps[(kk + tig    ) * FSTR + warp_m + g    ];
            uint32_t a1 = Ps[(kk + tig    ) * FSTR + warp_m + g + 8];
            uint32_t a2 = Ps[(kk + tig + 4) * FSTR + warp_m + g    ];
            uint32_t a3 = Ps[(kk + tig + 4) * FSTR + warp_m + g + 8];
#pragma unroll
            for (int nt = 0; nt < 8; nt++) {
                uint32_t b0 = f32_to_tf32(Vf[(kk + tig    ) * FSTR + nt * 8 + g]);
                uint32_t b1 = f32_to_tf32(Vf[(kk + tig + 4) * FSTR + nt * 8 + g]);
                mma_tf32(oacc[nt][0], oacc[nt][1], oacc[nt][2], oacc[nt][3],
                         a0, a1, a2, a3, b0, b1);
            }
        }
        if (have_next)
            __syncthreads();  // all warps done with stage kt&1 before it is reused
    }

    // ---- write O ----
    const float il0 = 1.0f / l0;
    const float il1 = 1.0f / l1;
    const size_t ob0 = ((size_t)(b * N + qi0 + warp_m + g    )) * D + h * HD;
    const size_t ob1 = ((size_t)(b * N + qi0 + warp_m + g + 8)) * D + h * HD;
#pragma unroll
    for (int nt = 0; nt < 8; nt++) {
        const int c0 = nt * 8 + tig * 2;
        *(float2*)(o + ob0 + c0) = make_float2(oacc[nt][0] * il0, oacc[nt][1] * il0);
        *(float2*)(o + ob1 + c0) = make_float2(oacc[nt][2] * il1, oacc[nt][3] * il1);
    }
}

}  // namespace

extern "C" void kernel_launch(void* const* d_in, const int* in_sizes, int n_in,
                              void* d_out, int out_size)
{
    const float* x_q  = (const float*)d_in[0];
    const float* x_kv = (const float*)d_in[1];
    const float* pos_enc = (const float*)d_in[2];
    const float* Wq = (const float*)d_in[3];
    const float* bq = (const float*)d_in[4];
    const float* Wk = (const float*)d_in[5];
    const float* bk = (const float*)d_in[6];
    const float* Wv = (const float*)d_in[7];
    const float* bv = (const float*)d_in[8];
    const float* Wo = (const float*)d_in[9];
    const float* bo = (const float*)d_in[10];
    const unsigned char* pad = (const unsigned char*)d_in[11];
    float* out = (float*)d_out;

    float *q, *k, *v, *o;
    cudaGetSymbolAddress((void**)&q, g_q);
    cudaGetSymbolAddress((void**)&k, g_k);
    cudaGetSymbolAddress((void**)&v, g_v);
    cudaGetSymbolAddress((void**)&o, g_o);

    const dim3 gemm_grid(D / TBN, M / TBM);  // (8, 64)

    cudaFuncSetAttribute(tf32_gemm_bias_kernel,
                         cudaFuncAttributeMaxDynamicSharedMemorySize, GEMM_SMEM);

    tf32_gemm_bias_kernel<<<gemm_grid, 256, GEMM_SMEM>>>(x_q,  Wq, bq, q, D, D);
    tf32_gemm_bias_kernel<<<gemm_grid, 256, GEMM_SMEM>>>(x_kv, Wk, bk, k, D, D);
    tf32_gemm_bias_kernel<<<gemm_grid, 256, GEMM_SMEM>>>(x_kv, Wv, bv, v, D, D);

    const int rope_total = B * N * H * (RD / 2);
    rope_kernel<<<(rope_total + 255) / 256, 256>>>(q, k, pos_enc);

    cudaFuncSetAttribute(flash_tc_kernel,
                         cudaFuncAttributeMaxDynamicSharedMemorySize, FLASH_SMEM);
    flash_tc_kernel<<<dim3(N / 64, H, B), 128, FLASH_SMEM>>>(q, k, v, pad, o);

    tf32_gemm_bias_kernel<<<gemm_grid, 256, GEMM_SMEM>>>(o, Wo, bo, out, D, D);
}

// round 13
// speedup vs baseline: 2.3681x; 1.0804x over previous
#include <cuda_runtime.h>
#include <math.h>
#include <stdint.h>

namespace {

constexpr int B  = 4;
constexpr int N  = 2048;
constexpr int D  = 1024;
constexpr int H  = 16;
constexpr int HD = 64;
constexpr int RD = 32;
constexpr int M  = B * N;   // 8192

// -------- scratch (device globals: allocation-guard safe) --------
__device__ float g_q[M * D];
__device__ float g_k[M * D];
__device__ float g_v[M * D];
__device__ float g_o[M * D];

__device__ __forceinline__ uint32_t f32_to_tf32(float x) {
    uint32_t y;
    asm("cvt.rna.tf32.f32 %0, %1;" : "=r"(y) : "f"(x));
    return y;
}

__device__ __forceinline__ void mma_tf32(
    float& d0, float& d1, float& d2, float& d3,
    uint32_t a0, uint32_t a1, uint32_t a2, uint32_t a3,
    uint32_t b0, uint32_t b1)
{
    asm volatile(
        "mma.sync.aligned.m16n8k8.row.col.f32.tf32.tf32.f32 "
        "{%0,%1,%2,%3}, {%4,%5,%6,%7}, {%8,%9}, {%0,%1,%2,%3};"
        : "+f"(d0), "+f"(d1), "+f"(d2), "+f"(d3)
        : "r"(a0), "r"(a1), "r"(a2), "r"(a3), "r"(b0), "r"(b1));
}

__device__ __forceinline__ void cp_async16(uint32_t smem_addr, const float* gptr) {
    asm volatile("cp.async.cg.shared.global [%0], [%1], 16;"
                 :: "r"(smem_addr), "l"(gptr));
}

// ===== TF32 tensor-core GEMM: 4-stage cp.async pipeline ====================
// 128x128x16 tile, 256 threads (8 warps), warp tile 64x32.
constexpr int TBM = 128, TBN = 128, TBK = 16;
constexpr int A_STR = 20;
constexpr int B_STR = 132;
constexpr int A_STAGEF = TBM * A_STR;            // 2560
constexpr int B_STAGEF = TBK * B_STR;            // 2112
constexpr int STAGEF   = A_STAGEF + B_STAGEF;    // 4672 floats
constexpr int GSTAGES  = 4;
constexpr int GEMM_SMEM = GSTAGES * STAGEF * (int)sizeof(float);  // 74752 B

// Shared GEMM body: C = A*W + bias, A:[8192 x 1024], W:[1024 x 1024]
__device__ __forceinline__ void gemm_body(
    const float* __restrict__ A, const float* __restrict__ W,
    const float* __restrict__ bias, float* __restrict__ C,
    float* smf)
{
    constexpr int Nd = D, Kd = D;
    uint32_t sbase;
    asm("{.reg .u64 t; cvta.to.shared.u64 t, %1; cvt.u32.u64 %0, t;}"
        : "=r"(sbase) : "l"(smf));

    const int tid  = threadIdx.x;
    const int wid  = tid >> 5;
    const int lane = tid & 31;
    const int g    = lane >> 2;
    const int tig  = lane & 3;

    const int warp_m = (wid >> 2) * 64;
    const int warp_n = (wid & 3) * 32;

    const int brow0 = blockIdx.y * TBM;
    const int bcol0 = blockIdx.x * TBN;

    float acc[4][4][4];
#pragma unroll
    for (int mt = 0; mt < 4; mt++)
#pragma unroll
        for (int nt = 0; nt < 4; nt++)
#pragma unroll
            for (int r = 0; r < 4; r++) acc[mt][nt][r] = 0.0f;

    const float* Aptr = A + (size_t)brow0 * Kd;
    const float* Wptr = W + bcol0;

    const int aRow0 = tid >> 2;
    const int aRow1 = aRow0 + 64;
    const int aCol  = (tid & 3) * 4;
    const int bRow0 = tid >> 5;
    const int bRow1 = bRow0 + 8;
    const int bCol  = (tid & 31) * 4;

    const int NT = Kd / TBK;   // 64

    auto issue_tile = [&](int t) {
        const int kt = t * TBK;
        const uint32_t ab = sbase + (uint32_t)((t % GSTAGES) * STAGEF) * 4u;
        const uint32_t bb = ab + (uint32_t)A_STAGEF * 4u;
        cp_async16(ab + (uint32_t)(aRow0 * A_STR + aCol) * 4u,
                   Aptr + (size_t)aRow0 * Kd + kt + aCol);
        cp_async16(ab + (uint32_t)(aRow1 * A_STR + aCol) * 4u,
                   Aptr + (size_t)aRow1 * Kd + kt + aCol);
        cp_async16(bb + (uint32_t)(bRow0 * B_STR + bCol) * 4u,
                   Wptr + (size_t)(kt + bRow0) * Nd + bCol);
        cp_async16(bb + (uint32_t)(bRow1 * B_STR + bCol) * 4u,
                   Wptr + (size_t)(kt + bRow1) * Nd + bCol);
        asm volatile("cp.async.commit_group;" ::: "memory");
    };

    issue_tile(0);
    issue_tile(1);
    issue_tile(2);

    for (int t = 0; t < NT; t++) {
        if (t >= NT - 3)
            asm volatile("cp.async.wait_group 0;" ::: "memory");
        else
            asm volatile("cp.async.wait_group 2;" ::: "memory");
        __syncthreads();

        const float* Af = smf + (t % GSTAGES) * STAGEF;
        const float* Bf = Af + A_STAGEF;

#pragma unroll
        for (int kk = 0; kk < TBK; kk += 8) {
            uint32_t af[4][4], bf[4][2];
#pragma unroll
            for (int mt = 0; mt < 4; mt++) {
                const int rm = warp_m + mt * 16;
                af[mt][0] = f32_to_tf32(Af[(rm + g    ) * A_STR + kk + tig    ]);
                af[mt][1] = f32_to_tf32(Af[(rm + g + 8) * A_STR + kk + tig    ]);
                af[mt][2] = f32_to_tf32(Af[(rm + g    ) * A_STR + kk + tig + 4]);
                af[mt][3] = f32_to_tf32(Af[(rm + g + 8) * A_STR + kk + tig + 4]);
            }
#pragma unroll
            for (int nt = 0; nt < 4; nt++) {
                const int cn = warp_n + nt * 8;
                bf[nt][0] = f32_to_tf32(Bf[(kk + tig    ) * B_STR + cn + g]);
                bf[nt][1] = f32_to_tf32(Bf[(kk + tig + 4) * B_STR + cn + g]);
            }
#pragma unroll
            for (int mt = 0; mt < 4; mt++)
#pragma unroll
                for (int nt = 0; nt < 4; nt++)
                    mma_tf32(acc[mt][nt][0], acc[mt][nt][1],
                             acc[mt][nt][2], acc[mt][nt][3],
                             af[mt][0], af[mt][1], af[mt][2], af[mt][3],
                             bf[nt][0], bf[nt][1]);
        }

        if (t + 3 < NT) issue_tile(t + 3);
    }

#pragma unroll
    for (int mt = 0; mt < 4; mt++) {
#pragma unroll
        for (int nt = 0; nt < 4; nt++) {
            const int col = bcol0 + warp_n + nt * 8 + tig * 2;
            const float b0 = bias[col], b1 = bias[col + 1];
            const size_t r0 = (size_t)(brow0 + warp_m + mt * 16 + g);
            const size_t r1 = r0 + 8;
            float2 v0 = make_float2(acc[mt][nt][0] + b0, acc[mt][nt][1] + b1);
            float2 v1 = make_float2(acc[mt][nt][2] + b0, acc[mt][nt][3] + b1);
            *(float2*)(C + r0 * Nd + col) = v0;
            *(float2*)(C + r1 * Nd + col) = v1;
        }
    }
}

// Fused Q/K/V projection: blockIdx.z selects which GEMM this CTA computes.
__global__ __launch_bounds__(256, 2) void qkv_gemm_kernel(
    const float* __restrict__ x_q, const float* __restrict__ x_kv,
    const float* __restrict__ Wq, const float* __restrict__ Wk,
    const float* __restrict__ Wv,
    const float* __restrict__ bq, const float* __restrict__ bk,
    const float* __restrict__ bv,
    float* __restrict__ q, float* __restrict__ k, float* __restrict__ v)
{
    extern __shared__ float smf[];
    const int z = blockIdx.z;
    const float* A    = (z == 0) ? x_q : x_kv;
    const float* W    = (z == 0) ? Wq : (z == 1) ? Wk : Wv;
    const float* bias = (z == 0) ? bq : (z == 1) ? bk : bv;
    float*       C    = (z == 0) ? q  : (z == 1) ? k  : v;
    gemm_body(A, W, bias, C, smf);
}

__global__ __launch_bounds__(256, 2) void o_gemm_kernel(
    const float* __restrict__ A, const float* __restrict__ W,
    const float* __restrict__ bias, float* __restrict__ C)
{
    extern __shared__ float smf[];
    gemm_body(A, W, bias, C, smf);
}

// ================= RoPE (rotation only; q scale applied in flash) =================
__global__ void rope_kernel(float* __restrict__ q, float* __restrict__ k,
                            const float* __restrict__ pos_enc)
{
    const int total = B * N * H * (RD / 2);
    int idx = blockIdx.x * blockDim.x + threadIdx.x;
    if (idx >= total) return;

    const int p = idx % (RD / 2);
    const int h = (idx / (RD / 2)) % H;
    const int n = (idx / ((RD / 2) * H)) % N;
    const int b = idx / ((RD / 2) * H * N);

    const float pe0 = pos_enc[n * RD + 2 * p];
    const float pe1 = pos_enc[n * RD + 2 * p + 1];
    const float c0 = cosf(pe0), s0 = sinf(pe0);
    const float c1 = cosf(pe1), s1 = sinf(pe1);

    const size_t base = ((size_t)(b * N + n)) * D + h * HD + 2 * p;

    float q0 = q[base], q1 = q[base + 1];
    q[base]     = q0 * c0 - q1 * s0;
    q[base + 1] = q1 * c1 + q0 * s1;

    float k0 = k[base], k1 = k[base + 1];
    k[base]     = k0 * c0 - k1 * s0;
    k[base + 1] = k1 * c1 + k0 * s1;
}

// ===== Flash attention (TF32 TC) with cp.async double-buffered K/V =========
constexpr int FSTR   = 72;
constexpr int KSTR   = 68;
constexpr int QS_OFF  = 0;
constexpr int PS_OFF  = 64 * FSTR;                 // 4608
constexpr int KF_OFF  = PS_OFF + 64 * FSTR;        // 9216
constexpr int KSTAGE  = 64 * KSTR;                 // 4352
constexpr int VF_OFF  = KF_OFF + 2 * KSTAGE;       // 17920
constexpr int VSTAGE  = 64 * FSTR;                 // 4608
constexpr int PAD_OFF = VF_OFF + 2 * VSTAGE;       // 27136
constexpr int FLASH_SMEM = (PAD_OFF + 128) * (int)sizeof(uint32_t);  // 109056 B

__global__ __launch_bounds__(128) void flash_tc_kernel(
    const float* __restrict__ q, const float* __restrict__ k,
    const float* __restrict__ v, const unsigned char* __restrict__ pad,
    float* __restrict__ o)
{
    extern __shared__ uint32_t smu[];
    uint32_t sbase;
    asm("{.reg .u64 t; cvta.to.shared.u64 t, %1; cvt.u32.u64 %0, t;}"
        : "=r"(sbase) : "l"(smu));

    uint32_t* Qs   = smu + QS_OFF;
    uint32_t* Ps   = smu + PS_OFF;
    float*    Padv = (float*)(smu + PAD_OFF);

    const int qt = blockIdx.x;
    const int h  = blockIdx.y;
    const int b  = blockIdx.z;
    const int qi0 = qt * 64;

    const int tid  = threadIdx.x;
    const int wid  = tid >> 5;
    const int lane = tid & 31;
    const int g    = lane >> 2;
    const int tig  = lane & 3;
    const int warp_m = wid * 16;

    auto issue_kv = [&](int t) {
        const int kj0 = t * 64;
        const size_t kb = ((size_t)(b * N + kj0)) * D + h * HD;
        const uint32_t kbuf = sbase + (uint32_t)(KF_OFF + (t & 1) * KSTAGE) * 4u;
        const uint32_t vbuf = sbase + (uint32_t)(VF_OFF + (t & 1) * VSTAGE) * 4u;
        for (int i = tid; i < 64 * 16; i += 128) {
            const int r  = i >> 4;
            const int c4 = (i & 15) * 4;
            cp_async16(kbuf + (uint32_t)(r * KSTR + c4) * 4u, k + kb + (size_t)r * D + c4);
            cp_async16(vbuf + (uint32_t)(r * FSTR + c4) * 4u, v + kb + (size_t)r * D + c4);
        }
        asm volatile("cp.async.commit_group;" ::: "memory");
        if (tid < 64)
            Padv[(t & 1) * 64 + tid] = pad[b * N + kj0 + tid] ? -3e38f : 3e38f;
    };

    issue_kv(0);

    const size_t qbase = ((size_t)(b * N + qi0)) * D + h * HD;
    for (int i = tid; i < 64 * 16; i += 128) {
        const int r  = i >> 4;
        const int c4 = (i & 15) * 4;
        float4 qv = *(const float4*)(q + qbase + (size_t)r * D + c4);
        Qs[(c4 + 0) * FSTR + r] = f32_to_tf32(qv.x * 0.125f);
        Qs[(c4 + 1) * FSTR + r] = f32_to_tf32(qv.y * 0.125f);
        Qs[(c4 + 2) * FSTR + r] = f32_to_tf32(qv.z * 0.125f);
        Qs[(c4 + 3) * FSTR + r] = f32_to_tf32(qv.w * 0.125f);
    }

    float m0 = -1e30f, m1 = -1e30f, l0 = 0.0f, l1 = 0.0f;
    float oacc[8][4];
#pragma unroll
    for (int nt = 0; nt < 8; nt++)
#pragma unroll
        for (int r = 0; r < 4; r++) oacc[nt][r] = 0.0f;

    const int ktiles = qt + 1;
    for (int kt = 0; kt < ktiles; kt++) {
        const bool have_next = (kt + 1) < ktiles;
        if (have_next) {
            issue_kv(kt + 1);
            asm volatile("cp.async.wait_group 1;" ::: "memory");
        } else {
            asm volatile("cp.async.wait_group 0;" ::: "memory");
        }
        __syncthreads();

        const float* Kf = (const float*)(smu + KF_OFF + (kt & 1) * KSTAGE);
        const float* Vf = (const float*)(smu + VF_OFF + (kt & 1) * VSTAGE);
        const float* Pv = Padv + (kt & 1) * 64;

        float s[8][4];
#pragma unroll
        for (int nt = 0; nt < 8; nt++)
#pragma unroll
            for (int r = 0; r < 4; r++) s[nt][r] = 0.0f;

#pragma unroll
        for (int kk = 0; kk < 64; kk += 8) {
            uint32_t a0 = Qs[(kk + tig    ) * FSTR + warp_m + g    ];
            uint32_t a1 = Qs[(kk + tig    ) * FSTR + warp_m + g + 8];
            uint32_t a2 = Qs[(kk + tig + 4) * FSTR + warp_m + g    ];
            uint32_t a3 = Qs[(kk + tig + 4) * FSTR + warp_m + g + 8];
#pragma unroll
            for (int nt = 0; nt < 8; nt++) {
                uint32_t b0 = f32_to_tf32(Kf[(nt * 8 + g) * KSTR + kk + tig    ]);
                uint32_t b1 = f32_to_tf32(Kf[(nt * 8 + g) * KSTR + kk + tig + 4]);
                mma_tf32(s[nt][0], s[nt][1], s[nt][2], s[nt][3],
                         a0, a1, a2, a3, b0, b1);
            }
        }

        const int kj0 = kt * 64;
        const int row0 = qi0 + warp_m + g;
        const int row1 = row0 + 8;
#pragma unroll
        for (int nt = 0; nt < 8; nt++) {
            const int c0 = nt * 8 + tig * 2;
            const float p0 = Pv[c0], p1 = Pv[c0 + 1];
            s[nt][0] = fminf(s[nt][0], p0);
            s[nt][1] = fminf(s[nt][1], p1);
            s[nt][2] = fminf(s[nt][2], p0);
            s[nt][3] = fminf(s[nt][3], p1);
        }
        if (kt == qt) {
#pragma unroll
            for (int nt = 0; nt < 8; nt++) {
                const int c0 = kj0 + nt * 8 + tig * 2;
                if (c0     > row0) s[nt][0] = -1e30f;
                if (c0 + 1 > row0) s[nt][1] = -1e30f;
                if (c0     > row1) s[nt][2] = -1e30f;
                if (c0 + 1 > row1) s[nt][3] = -1e30f;
            }
        }

        float mx0 = -1e30f, mx1 = -1e30f;
#pragma unroll
        for (int nt = 0; nt < 8; nt++) {
            mx0 = fmaxf(mx0, fmaxf(s[nt][0], s[nt][1]));
            mx1 = fmaxf(mx1, fmaxf(s[nt][2], s[nt][3]));
        }
        mx0 = fmaxf(mx0, __shfl_xor_sync(0xffffffffu, mx0, 1));
        mx0 = fmaxf(mx0, __shfl_xor_sync(0xffffffffu, mx0, 2));
        mx1 = fmaxf(mx1, __shfl_xor_sync(0xffffffffu, mx1, 1));
        mx1 = fmaxf(mx1, __shfl_xor_sync(0xffffffffu, mx1, 2));

        const float mn0 = fmaxf(m0, mx0);
        const float mn1 = fmaxf(m1, mx1);
        const float al0 = __expf(m0 - mn0);
        const float al1 = __expf(m1 - mn1);
        m0 = mn0; m1 = mn1;

        float sum0 = 0.0f, sum1 = 0.0f;
#pragma unroll
        for (int nt = 0; nt < 8; nt++) {
            s[nt][0] = __expf(s[nt][0] - mn0);
            s[nt][1] = __expf(s[nt][1] - mn0);
            s[nt][2] = __expf(s[nt][2] - mn1);
            s[nt][3] = __expf(s[nt][3] - mn1);
            sum0 += s[nt][0] + s[nt][1];
            sum1 += s[nt][2] + s[nt][3];
        }
        sum0 += __shfl_xor_sync(0xffffffffu, sum0, 1);
        sum0 += __shfl_xor_sync(0xffffffffu, sum0, 2);
        sum1 += __shfl_xor_sync(0xffffffffu, sum1, 1);
        sum1 += __shfl_xor_sync(0xffffffffu, sum1, 2);
        l0 = l0 * al0 + sum0;
        l1 = l1 * al1 + sum1;

#pragma unroll
        for (int nt = 0; nt < 8; nt++) {
#pragma unroll
            for (int r = 0; r < 4; r++) oacc[nt][r] *= (r < 2 ? al0 : al1);
        }

#pragma unroll
        for (int nt = 0; nt < 8; nt++) {
            const int c0 = nt * 8 + tig * 2;
            Ps[(c0    ) * FSTR + warp_m + g    ] = f32_to_tf32(s[nt][0]);
            Ps[(c0 + 1) * FSTR + warp_m + g    ] = f32_to_tf32(s[nt][1]);
            Ps[(c0    ) * FSTR + warp_m + g + 8] = f32_to_tf32(s[nt][2]);
            Ps[(c0 + 1) * FSTR + warp_m + g + 8] = f32_to_tf32(s[nt][3]);
        }
        __syncwarp();

#pragma unroll
        for (int kk = 0; kk < 64; kk += 8) {
            uint32_t a0 = Ps[(kk + tig    ) * FSTR + warp_m + g    ];
            uint32_t a1 = Ps[(kk + tig    ) * FSTR + warp_m + g + 8];
            uint32_t a2 = Ps[(kk + tig + 4) * FSTR + warp_m + g    ];
            uint32_t a3 = Ps[(kk + tig + 4) * FSTR + warp_m + g + 8];
#pragma unroll
            for (int nt = 0; nt < 8; nt++) {
                uint32_t b0 = f32_to_tf32(Vf[(kk + tig    ) * FSTR + nt * 8 + g]);
                uint32_t b1 = f32_to_tf32(Vf[(kk + tig + 4) * FSTR + nt * 8 + g]);
                mma_tf32(oacc[nt][0], oacc[nt][1], oacc[nt][2], oacc[nt][3],
                         a0, a1, a2, a3, b0, b1);
            }
        }
        if (have_next)
            __syncthreads();
    }

    const float il0 = 1.0f / l0;
    const float il1 = 1.0f / l1;
    const size_t ob0 = ((size_t)(b * N + qi0 + warp_m + g    )) * D + h * HD;
    const size_t ob1 = ((size_t)(b * N + qi0 + warp_m + g + 8)) * D + h * HD;
#pragma unroll
    for (int nt = 0; nt < 8; nt++) {
        const int c0 = nt * 8 + tig * 2;
        *(float2*)(o + ob0 + c0) = make_float2(oacc[nt][0] * il0, oacc[nt][1] * il0);
        *(float2*)(o + ob1 + c0) = make_float2(oacc[nt][2] * il1, oacc[nt][3] * il1);
    }
}

}  // namespace

extern "C" void kernel_launch(void* const* d_in, const int* in_sizes, int n_in,
                              void* d_out, int out_size)
{
    const float* x_q  = (const float*)d_in[0];
    const float* x_kv = (const float*)d_in[1];
    const float* pos_enc = (const float*)d_in[2];
    const float* Wq = (const float*)d_in[3];
    const float* bq = (const float*)d_in[4];
    const float* Wk = (const float*)d_in[5];
    const float* bk = (const float*)d_in[6];
    const float* Wv = (const float*)d_in[7];
    const float* bv = (const float*)d_in[8];
    const float* Wo = (const float*)d_in[9];
    const float* bo = (const float*)d_in[10];
    const unsigned char* pad = (const unsigned char*)d_in[11];
    float* out = (float*)d_out;

    float *q, *k, *v, *o;
    cudaGetSymbolAddress((void**)&q, g_q);
    cudaGetSymbolAddress((void**)&k, g_k);
    cudaGetSymbolAddress((void**)&v, g_v);
    cudaGetSymbolAddress((void**)&o, g_o);

    cudaFuncSetAttribute(qkv_gemm_kernel,
                         cudaFuncAttributeMaxDynamicSharedMemorySize, GEMM_SMEM);
    cudaFuncSetAttribute(o_gemm_kernel,
                         cudaFuncAttributeMaxDynamicSharedMemorySize, GEMM_SMEM);

    // fused Q/K/V projections: one launch, z selects the GEMM
    qkv_gemm_kernel<<<dim3(D / TBN, M / TBM, 3), 256, GEMM_SMEM>>>(
        x_q, x_kv, Wq, Wk, Wv, bq, bk, bv, q, k, v);

    const int rope_total = B * N * H * (RD / 2);
    rope_kernel<<<(rope_total + 255) / 256, 256>>>(q, k, pos_enc);

    cudaFuncSetAttribute(flash_tc_kernel,
                         cudaFuncAttributeMaxDynamicSharedMemorySize, FLASH_SMEM);
    flash_tc_kernel<<<dim3(N / 64, H, B), 128, FLASH_SMEM>>>(q, k, v, pad, o);

    o_gemm_kernel<<<dim3(D / TBN, M / TBM), 256, GEMM_SMEM>>>(o, Wo, bo, out);
}